// round 9
// baseline (speedup 1.0000x reference)
#include <cuda_runtime.h>
#include <cstdint>

#define MM_    3844
#define CIN_   128
#define COUT_  256
#define KTOT_  1152
#define BM_    256
#define BN_    128
#define NTHR_  512
#define NT_    72

#define WPS    8192                 // words per stage (A 4096 | W 2048 | E 2048)
#define OFFA(s) ((s) * WPS)
#define OFFW(s) ((s) * WPS + 4096)
#define OFFE(s) ((s) * WPS + 6144)
#define OFF_BBS (3 * WPS)
#define SMEM_BYTES ((OFF_BBS + BN_) * 4)   // 98816

__device__ __forceinline__ uint32_t to_tf32(float x) {
    uint32_t r;
    asm("cvt.rna.tf32.f32 %0, %1;" : "=r"(r) : "f"(x));
    return r;
}
__device__ __forceinline__ uint32_t smem_u32(const void* p) {
    uint32_t a;
    asm("{ .reg .u64 t; cvta.to.shared.u64 t, %1; cvt.u32.u64 %0, t; }" : "=r"(a) : "l"(p));
    return a;
}
__device__ __forceinline__ void cp16(uint32_t dst, const float* src, int src_bytes) {
    asm volatile("cp.async.cg.shared.global [%0], [%1], 16, %2;"
                 :: "r"(dst), "l"(src), "r"(src_bytes) : "memory");
}
#define CP_COMMIT() asm volatile("cp.async.commit_group;" ::: "memory")
#define CP_WAIT1()  asm volatile("cp.async.wait_group 1;" ::: "memory")

__device__ __forceinline__ void mma_tf32(float c[4],
                                         uint32_t a0, uint32_t a1, uint32_t a2, uint32_t a3,
                                         uint32_t b0, uint32_t b1) {
    asm volatile(
        "mma.sync.aligned.m16n8k8.row.col.f32.tf32.tf32.f32 "
        "{%0,%1,%2,%3}, {%4,%5,%6,%7}, {%8,%9}, {%0,%1,%2,%3};"
        : "+f"(c[0]), "+f"(c[1]), "+f"(c[2]), "+f"(c[3])
        : "r"(a0), "r"(a1), "r"(a2), "r"(a3), "r"(b0), "r"(b1));
}

__global__ void __launch_bounds__(NTHR_, 1)
conv_mma_kernel(const float* __restrict__ X, const float* __restrict__ W,
                const float* __restrict__ bias, const float* __restrict__ Werr,
                const float* __restrict__ Berr, float* __restrict__ out)
{
    extern __shared__ float smf[];
    const uint32_t sb = smem_u32(smf);
    float* const bbs = smf + OFF_BBS;

    const int tid  = threadIdx.x;
    const int lane = tid & 31;
    const int wid  = tid >> 5;        // 0..15
    const int wm   = wid >> 2;        // 0..3 (M dir, 64 rows)
    const int wn   = wid & 3;         // 0..3 (N dir, 32 cols)
    const int g    = lane >> 2;       // 0..7
    const int tq   = lane & 3;        // 0..3

    const int b  = blockIdx.z;
    const int m0 = blockIdx.y * BM_;
    const int n0 = blockIdx.x * BN_;

    if (tid < BN_) bbs[tid] = bias[n0 + tid] * Berr[b * COUT_ + n0 + tid];

    // ---- A prefetch mapping: thread -> (row = tid&255, chunk pair = (tid>>8)*2)
    const int arow = tid & 255;
    const int acp  = (tid >> 8) << 1;          // 0 or 2
    const int agm  = m0 + arow;
    const bool a_ok = (agm < MM_);
    const int amc = a_ok ? agm : 0;
    const int aho = amc / 62, awo = amc - aho * 62;
    const float* Xp = X + (((size_t)b * 64 + aho) * 64 + awo) * CIN_;
    const int a_sz = a_ok ? 16 : 0;
    const uint32_t aswz = ((uint32_t)arow >> 1) & 3;
    const uint32_t a_dst_row = sb + (uint32_t)arow * 64;    // 16 words = 64B per row

    // ---- W/E prefetch mapping: thread -> (k = tid>>5, nchunk = tid&31)
    const int pk  = tid >> 5;                // 0..15
    const int pnc = tid & 31;                // 0..31
    const uint32_t pdrow = (uint32_t)pk * 512
                         + 16 * ((uint32_t)pnc ^ ((uint32_t)(pk & 3) << 1));
    const float* Wp = W + n0 + 4 * pnc;
    const float* Ep = Werr + (size_t)b * ((size_t)KTOT_ * COUT_) + n0 + 4 * pnc;

    float acc[4][4][4];
    #pragma unroll
    for (int i = 0; i < 4; i++)
        #pragma unroll
        for (int j = 0; j < 4; j++)
            #pragma unroll
            for (int q = 0; q < 4; q++) acc[i][j][q] = 0.0f;

    auto prefetch = [&](int u, int s) {
        const int khw = u >> 3, cc = u & 7;
        const int kh = khw / 3, kw = khw - 3 * kh;
        // A: 2 chunks of row arow
        const float* asrc = Xp + (kh * 64 + kw) * CIN_ + cc * 16;
        const uint32_t ad = a_dst_row + (uint32_t)OFFA(s) * 4;
        #pragma unroll
        for (int c = acp; c < acp + 2; c++)
            cp16(ad + 16 * ((uint32_t)c ^ aswz), asrc + 4 * c, a_sz);
        // W, E: row pk
        const int kk = khw * CIN_ + cc * 16;
        const size_t gofs = (size_t)(kk + pk) * COUT_;
        cp16(sb + (uint32_t)OFFW(s) * 4 + pdrow, Wp + gofs, 16);
        cp16(sb + (uint32_t)OFFE(s) * 4 + pdrow, Ep + gofs, 16);
    };

    prefetch(0, 0); CP_COMMIT();
    prefetch(1, 1); CP_COMMIT();

    // frag addressing:
    // A: row r -> word r*16 + 4*(chunk ^ ((r>>1)&3)) + tq
    // B: k -> word k*128 + 4*((c>>2) ^ ((k&3)<<1)) + (c&3); (k&3)==tq for both k-groups
    const uint32_t bsw = (uint32_t)tq << 1;

    for (int t = 0; t < NT_; t++) {
        CP_WAIT1();
        __syncthreads();
        const int s = t % 3;
        if (t + 2 < NT_) prefetch(t + 2, (t + 2) % 3);
        CP_COMMIT();

        const float* Ab = smf + OFFA(s);
        const float* Wb = smf + OFFW(s);
        const float* Eb = smf + OFFE(s);

        #pragma unroll
        for (int k8 = 0; k8 < 2; k8++) {
            const uint32_t ch0 = (uint32_t)(k8 * 2);
            // ---- A fragments (raw -> cvt.rna)
            uint32_t af[4][4];
            #pragma unroll
            for (int mt = 0; mt < 4; mt++) {
                const int r  = wm * 64 + mt * 16 + g;
                const uint32_t sw = ((uint32_t)r >> 1) & 3;
                const float* a0p = Ab + r * 16 + tq;
                const float* a1p = Ab + (r + 8) * 16 + tq;
                af[mt][0] = to_tf32(a0p[4 * (ch0 ^ sw)]);
                af[mt][1] = to_tf32(a1p[4 * (ch0 ^ sw)]);
                af[mt][2] = to_tf32(a0p[4 * ((ch0 + 1) ^ sw)]);
                af[mt][3] = to_tf32(a1p[4 * ((ch0 + 1) ^ sw)]);
            }
            // ---- B fragments (W*Werr -> cvt.rna)
            uint32_t bf[4][2];
            #pragma unroll
            for (int nt = 0; nt < 4; nt++) {
                const int c = wn * 32 + nt * 8 + g;
                const uint32_t cw = 4 * (((uint32_t)c >> 2) ^ bsw) + ((uint32_t)c & 3);
                const int k1 = k8 * 8 + tq;
                const int k2 = k1 + 4;
                bf[nt][0] = to_tf32(Wb[k1 * 128 + cw] * Eb[k1 * 128 + cw]);
                bf[nt][1] = to_tf32(Wb[k2 * 128 + cw] * Eb[k2 * 128 + cw]);
            }
            #pragma unroll
            for (int mt = 0; mt < 4; mt++)
                #pragma unroll
                for (int nt = 0; nt < 4; nt++)
                    mma_tf32(acc[mt][nt], af[mt][0], af[mt][1], af[mt][2], af[mt][3],
                             bf[nt][0], bf[nt][1]);
        }
    }

    // ---- Epilogue: acc + bias*Berr -> out
    #pragma unroll
    for (int mt = 0; mt < 4; mt++) {
        #pragma unroll
        for (int h = 0; h < 2; h++) {
            int rg = m0 + wm * 64 + mt * 16 + g + h * 8;
            if (rg < MM_) {
                float* op = out + ((size_t)b * MM_ + rg) * COUT_ + n0 + wn * 32 + tq * 2;
                #pragma unroll
                for (int nt = 0; nt < 4; nt++) {
                    float2 bb = *(const float2*)&bbs[wn * 32 + nt * 8 + tq * 2];
                    float2 v;
                    v.x = acc[mt][nt][2 * h + 0] + bb.x;
                    v.y = acc[mt][nt][2 * h + 1] + bb.y;
                    *(float2*)(op + nt * 8) = v;
                }
            }
        }
    }
}

extern "C" void kernel_launch(void* const* d_in, const int* in_sizes, int n_in,
                              void* d_out, int out_size)
{
    const float* X    = (const float*)d_in[0];
    const float* W    = (const float*)d_in[1];
    const float* bias = (const float*)d_in[2];
    const float* Werr = (const float*)d_in[3];
    const float* Berr = (const float*)d_in[4];
    float* out = (float*)d_out;

    cudaFuncSetAttribute(conv_mma_kernel,
                         cudaFuncAttributeMaxDynamicSharedMemorySize, SMEM_BYTES);
    dim3 grid(COUT_ / BN_, (MM_ + BM_ - 1) / BM_, 64);   // (2, 16, 64)
    conv_mma_kernel<<<grid, NTHR_, SMEM_BYTES>>>(X, W, bias, Werr, Berr, out);
}

// round 10
// speedup vs baseline: 1.1580x; 1.1580x over previous
#include <cuda_runtime.h>
#include <cstdint>

#define MM_    3844
#define CIN_   128
#define COUT_  256
#define KTOT_  1152
#define BM_    256
#define BN_    128
#define NTHR_  256
#define NT_    72

#define WM_ELEMS  (64 * KTOT_ * COUT_)           // 18,874,368
#define XR_ELEMS  (64 * 64 * 64 * CIN_)          // 33,554,432

__device__ float g_Wm[WM_ELEMS];   // rna(W * Werr), [b][k][n]
__device__ float g_Xr[XR_ELEMS];   // rna(X)

#define WPS    6144                 // words per stage (A 4096 | Wm 2048)
#define OFFA(s) ((s) * WPS)
#define OFFB(s) ((s) * WPS + 4096)
#define OFF_BBS (3 * WPS)
#define SMEM_BYTES ((OFF_BBS + BN_) * 4)   // 74240

__device__ __forceinline__ uint32_t to_tf32(float x) {
    uint32_t r;
    asm("cvt.rna.tf32.f32 %0, %1;" : "=r"(r) : "f"(x));
    return r;
}
__device__ __forceinline__ uint32_t smem_u32(const void* p) {
    uint32_t a;
    asm("{ .reg .u64 t; cvta.to.shared.u64 t, %1; cvt.u32.u64 %0, t; }" : "=r"(a) : "l"(p));
    return a;
}
__device__ __forceinline__ void cp16(uint32_t dst, const float* src, int src_bytes) {
    asm volatile("cp.async.cg.shared.global [%0], [%1], 16, %2;"
                 :: "r"(dst), "l"(src), "r"(src_bytes) : "memory");
}
#define CP_COMMIT() asm volatile("cp.async.commit_group;" ::: "memory")
#define CP_WAIT1()  asm volatile("cp.async.wait_group 1;" ::: "memory")

__device__ __forceinline__ void mma_tf32(float c[4],
                                         uint32_t a0, uint32_t a1, uint32_t a2, uint32_t a3,
                                         uint32_t b0, uint32_t b1) {
    asm volatile(
        "mma.sync.aligned.m16n8k8.row.col.f32.tf32.tf32.f32 "
        "{%0,%1,%2,%3}, {%4,%5,%6,%7}, {%8,%9}, {%0,%1,%2,%3};"
        : "+f"(c[0]), "+f"(c[1]), "+f"(c[2]), "+f"(c[3])
        : "r"(a0), "r"(a1), "r"(a2), "r"(a3), "r"(b0), "r"(b1));
}

// ---- Pre-kernel 1: Wm = rna(W * Werr)
__global__ void __launch_bounds__(256, 4)
precompute_wm(const float* __restrict__ W, const float* __restrict__ Werr)
{
    const int b = blockIdx.y;
    const size_t j = ((size_t)blockIdx.x * 256 + threadIdx.x) * 4;   // < 294912
    const size_t gi = (size_t)b * (KTOT_ * COUT_) + j;
    float4 w = *(const float4*)(W + j);
    float4 e = *(const float4*)(Werr + gi);
    uint4 v = {to_tf32(w.x * e.x), to_tf32(w.y * e.y),
               to_tf32(w.z * e.z), to_tf32(w.w * e.w)};
    *(uint4*)(g_Wm + gi) = v;
}

// ---- Pre-kernel 2: Xr = rna(X)
__global__ void __launch_bounds__(256, 4)
precompute_xr(const float* __restrict__ X)
{
    const size_t i = ((size_t)blockIdx.x * 256 + threadIdx.x) * 4;
    float4 x = *(const float4*)(X + i);
    uint4 v = {to_tf32(x.x), to_tf32(x.y), to_tf32(x.z), to_tf32(x.w)};
    *(uint4*)(g_Xr + i) = v;
}

__global__ void __launch_bounds__(NTHR_, 1)
conv_mma_kernel(const float* __restrict__ bias,
                const float* __restrict__ Berr, float* __restrict__ out)
{
    extern __shared__ float smf[];
    const uint32_t sb = smem_u32(smf);
    float* const bbs = smf + OFF_BBS;

    const int tid  = threadIdx.x;
    const int lane = tid & 31;
    const int wid  = tid >> 5;        // 0..7
    const int wm   = wid >> 1;        // 0..3 (M dir, 64 rows)
    const int wn   = wid & 1;         // 0..1 (N dir, 64 cols)
    const int g    = lane >> 2;       // 0..7
    const int tq   = lane & 3;        // 0..3

    const int b  = blockIdx.z;
    const int m0 = blockIdx.y * BM_;
    const int n0 = blockIdx.x * BN_;

    if (tid < BN_) bbs[tid] = bias[n0 + tid] * Berr[b * COUT_ + n0 + tid];

    // ---- A prefetch mapping: thread = one m-row (tid), 4 chunks of 16B
    const int agm  = m0 + tid;
    const bool a_ok = (agm < MM_);
    const int amc = a_ok ? agm : 0;
    const int aho = amc / 62, awo = amc - aho * 62;
    const float* Xp = g_Xr + (((size_t)b * 64 + aho) * 64 + awo) * CIN_;
    const int a_sz = a_ok ? 16 : 0;
    const uint32_t aswz = ((uint32_t)tid >> 1) & 3;
    const uint32_t a_dst_row = sb + (uint32_t)tid * 64;     // 16 words = 64B per row

    // ---- Wm prefetch mapping: thread covers (k = tid>>5 and +8, nchunk = tid&31)
    const int pk  = tid >> 5;                // 0..7
    const int pnc = tid & 31;                // 0..31
    const uint32_t psw = (uint32_t)(pk & 3) << 1;            // same for pk and pk+8
    const float* Bp = g_Wm + (size_t)b * ((size_t)KTOT_ * COUT_) + n0 + 4 * pnc;

    float acc[4][8][4];
    #pragma unroll
    for (int i = 0; i < 4; i++)
        #pragma unroll
        for (int j = 0; j < 8; j++)
            #pragma unroll
            for (int q = 0; q < 4; q++) acc[i][j][q] = 0.0f;

    auto prefetch = [&](int u, int s) {
        const int khw = u >> 3, cc = u & 7;
        const int kh = khw / 3, kw = khw - 3 * kh;
        // A: 4 chunks of row tid
        const float* asrc = Xp + (kh * 64 + kw) * CIN_ + cc * 16;
        const uint32_t ad = a_dst_row + (uint32_t)OFFA(s) * 4;
        #pragma unroll
        for (int c = 0; c < 4; c++)
            cp16(ad + 16 * ((uint32_t)c ^ aswz), asrc + 4 * c, a_sz);
        // Wm: rows pk and pk+8
        const int kk = khw * CIN_ + cc * 16;
        #pragma unroll
        for (int h = 0; h < 2; h++) {
            const int k = pk + 8 * h;
            const size_t gofs = (size_t)(kk + k) * COUT_;
            const uint32_t drow = (uint32_t)k * 512 + 16 * ((uint32_t)pnc ^ psw);
            cp16(sb + (uint32_t)OFFB(s) * 4 + drow, Bp + gofs, 16);
        }
    };

    prefetch(0, 0); CP_COMMIT();
    prefetch(1, 1); CP_COMMIT();

    // frag addressing (word indices), operands are pre-rounded tf32 bit patterns:
    // A: row r -> r*16 + 4*(chunk ^ ((r>>1)&3)) + tq
    // B: k -> k*128 + 4*((c>>2) ^ ((k&3)<<1)) + (c&3); (k&3)==tq for both k-groups
    const uint32_t bsw = (uint32_t)tq << 1;

    for (int t = 0; t < NT_; t++) {
        CP_WAIT1();
        __syncthreads();
        const int s = t % 3;
        if (t + 2 < NT_) prefetch(t + 2, (t + 2) % 3);
        CP_COMMIT();

        const uint32_t* Ab = (const uint32_t*)(smf + OFFA(s));
        const uint32_t* Bb = (const uint32_t*)(smf + OFFB(s));

        #pragma unroll
        for (int k8 = 0; k8 < 2; k8++) {
            const uint32_t ch0 = (uint32_t)(k8 * 2);
            // ---- A fragments (pre-rounded, plain loads)
            uint32_t af[4][4];
            #pragma unroll
            for (int mt = 0; mt < 4; mt++) {
                const int r  = wm * 64 + mt * 16 + g;
                const uint32_t sw = ((uint32_t)r >> 1) & 3;
                const uint32_t* a0p = Ab + r * 16 + tq;
                const uint32_t* a1p = Ab + (r + 8) * 16 + tq;
                af[mt][0] = a0p[4 * (ch0 ^ sw)];
                af[mt][1] = a1p[4 * (ch0 ^ sw)];
                af[mt][2] = a0p[4 * ((ch0 + 1) ^ sw)];
                af[mt][3] = a1p[4 * ((ch0 + 1) ^ sw)];
            }
            // ---- B fragments (pre-rounded W*Werr, plain loads)
            uint32_t bf[8][2];
            #pragma unroll
            for (int nt = 0; nt < 8; nt++) {
                const int c = wn * 64 + nt * 8 + g;
                const uint32_t cw = 4 * (((uint32_t)c >> 2) ^ bsw) + ((uint32_t)c & 3);
                const int k1 = k8 * 8 + tq;
                const int k2 = k1 + 4;
                bf[nt][0] = Bb[k1 * 128 + cw];
                bf[nt][1] = Bb[k2 * 128 + cw];
            }
            #pragma unroll
            for (int mt = 0; mt < 4; mt++)
                #pragma unroll
                for (int nt = 0; nt < 8; nt++)
                    mma_tf32(acc[mt][nt], af[mt][0], af[mt][1], af[mt][2], af[mt][3],
                             bf[nt][0], bf[nt][1]);
        }
    }

    // ---- Epilogue: acc + bias*Berr -> out
    #pragma unroll
    for (int mt = 0; mt < 4; mt++) {
        #pragma unroll
        for (int h = 0; h < 2; h++) {
            int rg = m0 + wm * 64 + mt * 16 + g + h * 8;
            if (rg < MM_) {
                float* op = out + ((size_t)b * MM_ + rg) * COUT_ + n0 + wn * 64 + tq * 2;
                #pragma unroll
                for (int nt = 0; nt < 8; nt++) {
                    float2 bb = *(const float2*)&bbs[wn * 64 + nt * 8 + tq * 2];
                    float2 v;
                    v.x = acc[mt][nt][2 * h + 0] + bb.x;
                    v.y = acc[mt][nt][2 * h + 1] + bb.y;
                    *(float2*)(op + nt * 8) = v;
                }
            }
        }
    }
}

extern "C" void kernel_launch(void* const* d_in, const int* in_sizes, int n_in,
                              void* d_out, int out_size)
{
    const float* X    = (const float*)d_in[0];
    const float* W    = (const float*)d_in[1];
    const float* bias = (const float*)d_in[2];
    const float* Werr = (const float*)d_in[3];
    const float* Berr = (const float*)d_in[4];
    float* out = (float*)d_out;

    // Pre-kernels: rounded operands into __device__ scratch
    {
        dim3 gw((KTOT_ * COUT_) / (256 * 4), 64);   // (288, 64)
        precompute_wm<<<gw, 256>>>(W, Werr);
        precompute_xr<<<XR_ELEMS / (256 * 4), 256>>>(X);
    }

    cudaFuncSetAttribute(conv_mma_kernel,
                         cudaFuncAttributeMaxDynamicSharedMemorySize, SMEM_BYTES);
    dim3 grid(COUT_ / BN_, (MM_ + BM_ - 1) / BM_, 64);   // (2, 16, 64)
    conv_mma_kernel<<<grid, NTHR_, SMEM_BYTES>>>(bias, Berr, out);
}

// round 11
// speedup vs baseline: 2.0044x; 1.7309x over previous
#include <cuda_runtime.h>
#include <cuda_fp16.h>
#include <cstdint>

#define MM_    3844
#define CIN_   128
#define COUT_  256
#define KTOT_  1152
#define BM_    256
#define BN_    128
#define NTHR_  256
#define NT_    72

#define WM_ELEMS  (64 * KTOT_ * COUT_)           // 18,874,368 halfs, [b][n][k] interleaved
#define XR_ELEMS  (64 * 64 * 64 * CIN_)          // 33,554,432 halfs, interleaved per 16

__device__ __half g_Wmh[WM_ELEMS];
__device__ __half g_Xh[XR_ELEMS];

#define STG_BYTES 36864          // A 256*96 | B 128*96
#define A_OFF(s)  ((s) * STG_BYTES)
#define B_OFF(s)  ((s) * STG_BYTES + 24576)
#define BBS_OFF   (3 * STG_BYTES)          // 110592
#define SMEM_BYTES (BBS_OFF + 512)         // 111104

__device__ __forceinline__ uint32_t pack_h2(float hi, float lo) {
    uint32_t r;
    asm("cvt.rn.f16x2.f32 %0, %1, %2;" : "=r"(r) : "f"(hi), "f"(lo));
    return r;
}
__device__ __forceinline__ uint32_t smem_u32(const void* p) {
    uint32_t a;
    asm("{ .reg .u64 t; cvta.to.shared.u64 t, %1; cvt.u32.u64 %0, t; }" : "=r"(a) : "l"(p));
    return a;
}
__device__ __forceinline__ void cp16(uint32_t dst, const void* src, int src_bytes) {
    asm volatile("cp.async.cg.shared.global [%0], [%1], 16, %2;"
                 :: "r"(dst), "l"(src), "r"(src_bytes) : "memory");
}
#define CP_COMMIT() asm volatile("cp.async.commit_group;" ::: "memory")
#define CP_WAIT1()  asm volatile("cp.async.wait_group 1;" ::: "memory")

__device__ __forceinline__ void mma_f16(float c[4],
                                        uint32_t a0, uint32_t a1, uint32_t a2, uint32_t a3,
                                        uint32_t b0, uint32_t b1) {
    asm volatile(
        "mma.sync.aligned.m16n8k16.row.col.f32.f16.f16.f32 "
        "{%0,%1,%2,%3}, {%4,%5,%6,%7}, {%8,%9}, {%0,%1,%2,%3};"
        : "+f"(c[0]), "+f"(c[1]), "+f"(c[2]), "+f"(c[3])
        : "r"(a0), "r"(a1), "r"(a2), "r"(a3), "r"(b0), "r"(b1));
}

// ---- Pre-kernel 1: Xh = fp16(X), k-interleaved per 16-chunk
// chunk halfs: [v0,v1,v8,v9, v2,v3,v10,v11, v4,v5,v12,v13, v6,v7,v14,v15]
__global__ void __launch_bounds__(256, 4)
precompute_xh(const float* __restrict__ X)
{
    const size_t i = (size_t)blockIdx.x * 256 + threadIdx.x;   // chunk id
    const float* xp = X + i * 16;
    float v[16];
    #pragma unroll
    for (int j = 0; j < 16; j += 4) {
        float4 f = *(const float4*)(xp + j);
        v[j] = f.x; v[j+1] = f.y; v[j+2] = f.z; v[j+3] = f.w;
    }
    uint4 o0, o1;
    o0.x = pack_h2(v[1],  v[0]);  o0.y = pack_h2(v[9],  v[8]);
    o0.z = pack_h2(v[3],  v[2]);  o0.w = pack_h2(v[11], v[10]);
    o1.x = pack_h2(v[5],  v[4]);  o1.y = pack_h2(v[13], v[12]);
    o1.z = pack_h2(v[7],  v[6]);  o1.w = pack_h2(v[15], v[14]);
    uint4* op = (uint4*)(g_Xh + i * 16);
    op[0] = o0; op[1] = o1;
}

// ---- Pre-kernel 2: Wmh[b][n][k] = fp16(W*Werr) transposed, k-interleaved per 16
__global__ void __launch_bounds__(256, 2)
precompute_wmh(const float* __restrict__ W, const float* __restrict__ Werr)
{
    __shared__ __half tile[32 * 66];
    const int t  = threadIdx.x;
    const int b  = blockIdx.z;
    const int k0 = blockIdx.x * 32;
    const int n0 = blockIdx.y * 64;

    // read 32k x 64n, multiply, convert
    #pragma unroll
    for (int it = 0; it < 2; it++) {
        const int row = (t >> 4) + 16 * it;       // k_local
        const int nl  = (t & 15) * 4;
        const size_t gi = (size_t)(k0 + row) * COUT_ + n0 + nl;
        float4 w = *(const float4*)(W + gi);
        float4 e = *(const float4*)(Werr + (size_t)b * (KTOT_ * COUT_) + gi);
        __half* sp = tile + row * 66 + nl;
        *(uint32_t*)(sp + 0) = pack_h2(w.y * e.y, w.x * e.x);
        *(uint32_t*)(sp + 2) = pack_h2(w.w * e.w, w.z * e.z);
    }
    __syncthreads();

    // write: thread -> (n_local = t>>2, q = (t&3)>>1, half-of-chunk c2 = t&1)
    const int nl = t >> 2;
    const int q  = (t & 3) >> 1;
    const int c2 = t & 1;
    // k list for this 8-half group (within 16-chunk, interleaved)
    const int base = c2 * 4;   // c2=0: {0,1,8,9,2,3,10,11}; c2=1: {4,5,12,13,6,7,14,15}
    int kl[8];
    #pragma unroll
    for (int j = 0; j < 4; j += 2) {
        kl[2*j+0] = base + j;     kl[2*j+1] = base + j + 1;
        kl[2*j+2] = base + j + 8; kl[2*j+3] = base + j + 9;
    }
    const __half* sp = tile + (16 * q) * 66 + nl;
    uint4 o;
    o.x = pack_h2(__half2float(sp[kl[1] * 66]), __half2float(sp[kl[0] * 66]));
    o.y = pack_h2(__half2float(sp[kl[3] * 66]), __half2float(sp[kl[2] * 66]));
    o.z = pack_h2(__half2float(sp[kl[5] * 66]), __half2float(sp[kl[4] * 66]));
    o.w = pack_h2(__half2float(sp[kl[7] * 66]), __half2float(sp[kl[6] * 66]));
    const size_t hidx = (size_t)(b * COUT_ + n0 + nl) * KTOT_ + k0 + 16 * q + 8 * c2;
    *(uint4*)(g_Wmh + hidx) = o;
}

__global__ void __launch_bounds__(NTHR_, 1)
conv_mma_kernel(const float* __restrict__ bias,
                const float* __restrict__ Berr, float* __restrict__ out)
{
    extern __shared__ char smc[];
    const uint32_t sb = smem_u32(smc);
    float* const bbs = (float*)(smc + BBS_OFF);

    const int tid  = threadIdx.x;
    const int lane = tid & 31;
    const int wid  = tid >> 5;        // 0..7
    const int wm   = wid >> 1;        // 0..3 (M dir, 64 rows)
    const int wn   = wid & 1;         // 0..1 (N dir, 64 cols)
    const int g    = lane >> 2;       // 0..7
    const int tq   = lane & 3;        // 0..3

    const int b  = blockIdx.z;
    const int m0 = blockIdx.y * BM_;
    const int n0 = blockIdx.x * BN_;

    if (tid < BN_) bbs[tid] = bias[n0 + tid] * Berr[b * COUT_ + n0 + tid];

    // ---- A prefetch: thread = row tid, 2 cp16 (32B of halfs)
    const int agm  = m0 + tid;
    const bool a_ok = (agm < MM_);
    const int amc = a_ok ? agm : 0;
    const int aho = amc / 62, awo = amc - aho * 62;
    const __half* Xp = g_Xh + (((size_t)b * 64 + aho) * 64 + awo) * CIN_;
    const int a_sz = a_ok ? 16 : 0;
    const uint32_t a_dst = sb + (uint32_t)tid * 96;

    // ---- B prefetch: thread = (row = tid>>1, chunk16 = tid&1), 1 cp16
    const int brow = tid >> 1;
    const int bc   = tid & 1;
    const __half* Bp = g_Wmh + (size_t)(b * COUT_ + n0 + brow) * KTOT_ + 8 * bc;
    const uint32_t b_dst = sb + (uint32_t)brow * 96 + 16 * bc;

    float acc[4][8][4];
    #pragma unroll
    for (int i = 0; i < 4; i++)
        #pragma unroll
        for (int j = 0; j < 8; j++)
            #pragma unroll
            for (int q = 0; q < 4; q++) acc[i][j][q] = 0.0f;

    auto prefetch = [&](int u, int s) {
        const int khw = u >> 3, cc = u & 7;
        const int kh = khw / 3, kw = khw - 3 * kh;
        const __half* asrc = Xp + (kh * 64 + kw) * CIN_ + cc * 16;
        cp16(a_dst + A_OFF(s),      asrc,     a_sz);
        cp16(a_dst + A_OFF(s) + 16, asrc + 8, a_sz);
        const int kk = khw * CIN_ + cc * 16;
        cp16(b_dst + B_OFF(s), Bp + kk, 16);
    };

    prefetch(0, 0); CP_COMMIT();
    prefetch(1, 1); CP_COMMIT();

    for (int t = 0; t < NT_; t++) {
        CP_WAIT1();
        __syncthreads();
        const int s = t % 3;
        if (t + 2 < NT_) prefetch(t + 2, (t + 2) % 3);
        CP_COMMIT();

        const char* Ab = smc + A_OFF(s);
        const char* Bb = smc + B_OFF(s);

        // fragments: one LDS.64 each; row stride 96B -> conflict-free phases
        uint2 ar[4], a8[4], bf[8];
        #pragma unroll
        for (int mt = 0; mt < 4; mt++) {
            const int r = wm * 64 + mt * 16 + g;
            ar[mt] = *(const uint2*)(Ab + r * 96 + 8 * tq);
            a8[mt] = *(const uint2*)(Ab + (r + 8) * 96 + 8 * tq);
        }
        #pragma unroll
        for (int nt = 0; nt < 8; nt++) {
            const int c = wn * 64 + nt * 8 + g;
            bf[nt] = *(const uint2*)(Bb + c * 96 + 8 * tq);
        }
        #pragma unroll
        for (int mt = 0; mt < 4; mt++)
            #pragma unroll
            for (int nt = 0; nt < 8; nt++)
                mma_f16(acc[mt][nt], ar[mt].x, a8[mt].x, ar[mt].y, a8[mt].y,
                        bf[nt].x, bf[nt].y);
    }

    // ---- Epilogue: acc + bias*Berr -> out
    #pragma unroll
    for (int mt = 0; mt < 4; mt++) {
        #pragma unroll
        for (int h = 0; h < 2; h++) {
            int rg = m0 + wm * 64 + mt * 16 + g + h * 8;
            if (rg < MM_) {
                float* op = out + ((size_t)b * MM_ + rg) * COUT_ + n0 + wn * 64 + tq * 2;
                #pragma unroll
                for (int nt = 0; nt < 8; nt++) {
                    float2 bb = *(const float2*)&bbs[wn * 64 + nt * 8 + tq * 2];
                    float2 v;
                    v.x = acc[mt][nt][2 * h + 0] + bb.x;
                    v.y = acc[mt][nt][2 * h + 1] + bb.y;
                    *(float2*)(op + nt * 8) = v;
                }
            }
        }
    }
}

extern "C" void kernel_launch(void* const* d_in, const int* in_sizes, int n_in,
                              void* d_out, int out_size)
{
    const float* X    = (const float*)d_in[0];
    const float* W    = (const float*)d_in[1];
    const float* bias = (const float*)d_in[2];
    const float* Werr = (const float*)d_in[3];
    const float* Berr = (const float*)d_in[4];
    float* out = (float*)d_out;

    precompute_xh<<<XR_ELEMS / (16 * 256), 256>>>(X);
    {
        dim3 gw(KTOT_ / 32, COUT_ / 64, 64);   // (36, 4, 64)
        precompute_wmh<<<gw, 256>>>(W, Werr);
    }

    cudaFuncSetAttribute(conv_mma_kernel,
                         cudaFuncAttributeMaxDynamicSharedMemorySize, SMEM_BYTES);
    dim3 grid(COUT_ / BN_, (MM_ + BM_ - 1) / BM_, 64);   // (2, 16, 64)
    conv_mma_kernel<<<grid, NTHR_, SMEM_BYTES>>>(bias, Berr, out);
}

// round 12
// speedup vs baseline: 2.0414x; 1.0184x over previous
#include <cuda_runtime.h>
#include <cuda_fp16.h>
#include <cstdint>

#define MM_    3844
#define CIN_   128
#define COUT_  256
#define KTOT_  1152
#define BM_    256
#define BN_    128
#define NTHR_  256
#define NT_    36                   // k tiles: 9 khw * 4 ci-chunks of 32

#define WM_ELEMS  (64 * KTOT_ * COUT_)
#define XR_ELEMS  (64 * 64 * 64 * CIN_)

__device__ __half g_Wmh[WM_ELEMS];   // [b][n][k], k-interleaved per 16
__device__ __half g_Xh[XR_ELEMS];    // [b][h][w][ci], k-interleaved per 16

#define STG_BYTES 36864          // A 256*96 | B 128*96 (64B data per 96B row)
#define A_OFF(s)  ((s) * STG_BYTES)
#define B_OFF(s)  ((s) * STG_BYTES + 24576)
#define BBS_OFF   (3 * STG_BYTES)          // 110592
#define SMEM_BYTES (BBS_OFF + 512)         // 111104

__device__ __forceinline__ uint32_t pack_h2(float hi, float lo) {
    uint32_t r;
    asm("cvt.rn.f16x2.f32 %0, %1, %2;" : "=r"(r) : "f"(hi), "f"(lo));
    return r;
}
__device__ __forceinline__ uint32_t smem_u32(const void* p) {
    uint32_t a;
    asm("{ .reg .u64 t; cvta.to.shared.u64 t, %1; cvt.u32.u64 %0, t; }" : "=r"(a) : "l"(p));
    return a;
}
__device__ __forceinline__ void cp16(uint32_t dst, const void* src, int src_bytes) {
    asm volatile("cp.async.cg.shared.global [%0], [%1], 16, %2;"
                 :: "r"(dst), "l"(src), "r"(src_bytes) : "memory");
}
#define CP_COMMIT() asm volatile("cp.async.commit_group;" ::: "memory")
#define CP_WAIT1()  asm volatile("cp.async.wait_group 1;" ::: "memory")

__device__ __forceinline__ void mma_f16(float c[4],
                                        uint32_t a0, uint32_t a1, uint32_t a2, uint32_t a3,
                                        uint32_t b0, uint32_t b1) {
    asm volatile(
        "mma.sync.aligned.m16n8k16.row.col.f32.f16.f16.f32 "
        "{%0,%1,%2,%3}, {%4,%5,%6,%7}, {%8,%9}, {%0,%1,%2,%3};"
        : "+f"(c[0]), "+f"(c[1]), "+f"(c[2]), "+f"(c[3])
        : "r"(a0), "r"(a1), "r"(a2), "r"(a3), "r"(b0), "r"(b1));
}

// ---- Pre-kernel 1: Xh = fp16(X), k-interleaved per 16-chunk
__global__ void __launch_bounds__(256, 4)
precompute_xh(const float* __restrict__ X)
{
    const size_t i = (size_t)blockIdx.x * 256 + threadIdx.x;   // chunk id
    const float* xp = X + i * 16;
    float v[16];
    #pragma unroll
    for (int j = 0; j < 16; j += 4) {
        float4 f = *(const float4*)(xp + j);
        v[j] = f.x; v[j+1] = f.y; v[j+2] = f.z; v[j+3] = f.w;
    }
    uint4 o0, o1;
    o0.x = pack_h2(v[1],  v[0]);  o0.y = pack_h2(v[9],  v[8]);
    o0.z = pack_h2(v[3],  v[2]);  o0.w = pack_h2(v[11], v[10]);
    o1.x = pack_h2(v[5],  v[4]);  o1.y = pack_h2(v[13], v[12]);
    o1.z = pack_h2(v[7],  v[6]);  o1.w = pack_h2(v[15], v[14]);
    uint4* op = (uint4*)(g_Xh + i * 16);
    op[0] = o0; op[1] = o1;
}

// ---- Pre-kernel 2: Wmh[b][n][k] = fp16(W*Werr) transposed, k-interleaved per 16
__global__ void __launch_bounds__(256, 2)
precompute_wmh(const float* __restrict__ W, const float* __restrict__ Werr)
{
    __shared__ __half tile[32 * 66];
    const int t  = threadIdx.x;
    const int b  = blockIdx.z;
    const int k0 = blockIdx.x * 32;
    const int n0 = blockIdx.y * 64;

    #pragma unroll
    for (int it = 0; it < 2; it++) {
        const int row = (t >> 4) + 16 * it;       // k_local
        const int nl  = (t & 15) * 4;
        const size_t gi = (size_t)(k0 + row) * COUT_ + n0 + nl;
        float4 w = *(const float4*)(W + gi);
        float4 e = *(const float4*)(Werr + (size_t)b * (KTOT_ * COUT_) + gi);
        __half* sp = tile + row * 66 + nl;
        *(uint32_t*)(sp + 0) = pack_h2(w.y * e.y, w.x * e.x);
        *(uint32_t*)(sp + 2) = pack_h2(w.w * e.w, w.z * e.z);
    }
    __syncthreads();

    const int nl = t >> 2;
    const int q  = (t & 3) >> 1;
    const int c2 = t & 1;
    const int base = c2 * 4;
    int kl[8];
    #pragma unroll
    for (int j = 0; j < 4; j += 2) {
        kl[2*j+0] = base + j;     kl[2*j+1] = base + j + 1;
        kl[2*j+2] = base + j + 8; kl[2*j+3] = base + j + 9;
    }
    const __half* sp = tile + (16 * q) * 66 + nl;
    uint4 o;
    o.x = pack_h2(__half2float(sp[kl[1] * 66]), __half2float(sp[kl[0] * 66]));
    o.y = pack_h2(__half2float(sp[kl[3] * 66]), __half2float(sp[kl[2] * 66]));
    o.z = pack_h2(__half2float(sp[kl[5] * 66]), __half2float(sp[kl[4] * 66]));
    o.w = pack_h2(__half2float(sp[kl[7] * 66]), __half2float(sp[kl[6] * 66]));
    const size_t hidx = (size_t)(b * COUT_ + n0 + nl) * KTOT_ + k0 + 16 * q + 8 * c2;
    *(uint4*)(g_Wmh + hidx) = o;
}

__global__ void __launch_bounds__(NTHR_, 1)
conv_mma_kernel(const float* __restrict__ bias,
                const float* __restrict__ Berr, float* __restrict__ out)
{
    extern __shared__ char smc[];
    const uint32_t sb = smem_u32(smc);
    float* const bbs = (float*)(smc + BBS_OFF);

    const int tid  = threadIdx.x;
    const int lane = tid & 31;
    const int wid  = tid >> 5;        // 0..7
    const int wm   = wid >> 1;        // 0..3 (M dir, 64 rows)
    const int wn   = wid & 1;         // 0..1 (N dir, 64 cols)
    const int g    = lane >> 2;       // 0..7
    const int tq   = lane & 3;        // 0..3

    const int b  = blockIdx.z;
    const int m0 = blockIdx.y * BM_;
    const int n0 = blockIdx.x * BN_;

    if (tid < BN_) bbs[tid] = bias[n0 + tid] * Berr[b * COUT_ + n0 + tid];

    // ---- A prefetch: thread = row tid, 4 cp16 (64B = 32 halfs)
    const int agm  = m0 + tid;
    const bool a_ok = (agm < MM_);
    const int amc = a_ok ? agm : 0;
    const int aho = amc / 62, awo = amc - aho * 62;
    const __half* Xp = g_Xh + (((size_t)b * 64 + aho) * 64 + awo) * CIN_;
    const int a_sz = a_ok ? 16 : 0;
    const uint32_t a_dst = sb + (uint32_t)tid * 96;

    // ---- B prefetch: thread = (row = tid>>1, 16-chunk = tid&1), 2 cp16
    const int brow = tid >> 1;
    const int bc   = tid & 1;
    const __half* Bp = g_Wmh + (size_t)(b * COUT_ + n0 + brow) * KTOT_ + 16 * bc;
    const uint32_t b_dst = sb + (uint32_t)brow * 96 + 32 * bc;

    float acc[4][8][4];
    #pragma unroll
    for (int i = 0; i < 4; i++)
        #pragma unroll
        for (int j = 0; j < 8; j++)
            #pragma unroll
            for (int q = 0; q < 4; q++) acc[i][j][q] = 0.0f;

    auto prefetch = [&](int u, int s) {
        const int khw = u >> 2, cc = u & 3;          // 32-halfs chunk
        const int kh = khw / 3, kw = khw - 3 * kh;
        const __half* asrc = Xp + (kh * 64 + kw) * CIN_ + cc * 32;
        const uint32_t ad = a_dst + A_OFF(s);
        #pragma unroll
        for (int j = 0; j < 4; j++)
            cp16(ad + 16 * j, asrc + 8 * j, a_sz);
        const int kk = khw * CIN_ + cc * 32;
        const uint32_t bd = b_dst + B_OFF(s);
        cp16(bd,      Bp + kk,     16);
        cp16(bd + 16, Bp + kk + 8, 16);
    };

    prefetch(0, 0); CP_COMMIT();
    prefetch(1, 1); CP_COMMIT();

    auto tile_step = [&](int t, int s) {
        CP_WAIT1();
        __syncthreads();
        if (t + 2 < NT_) prefetch(t + 2, (t + 2) % 3);
        CP_COMMIT();

        const char* Ab = smc + A_OFF(s);
        const char* Bb = smc + B_OFF(s);

        #pragma unroll
        for (int c16 = 0; c16 < 2; c16++) {
            const int co = 32 * c16 + 8 * tq;
            uint2 ar[4], a8[4], bf[8];
            #pragma unroll
            for (int mt = 0; mt < 4; mt++) {
                const int r = wm * 64 + mt * 16 + g;
                ar[mt] = *(const uint2*)(Ab + r * 96 + co);
                a8[mt] = *(const uint2*)(Ab + (r + 8) * 96 + co);
            }
            #pragma unroll
            for (int nt = 0; nt < 8; nt++) {
                const int c = wn * 64 + nt * 8 + g;
                bf[nt] = *(const uint2*)(Bb + c * 96 + co);
            }
            #pragma unroll
            for (int mt = 0; mt < 4; mt++)
                #pragma unroll
                for (int nt = 0; nt < 8; nt++)
                    mma_f16(acc[mt][nt], ar[mt].x, a8[mt].x, ar[mt].y, a8[mt].y,
                            bf[nt].x, bf[nt].y);
        }
    };

    #pragma unroll 1
    for (int tb = 0; tb < NT_; tb += 3) {
        tile_step(tb + 0, 0);
        tile_step(tb + 1, 1);
        tile_step(tb + 2, 2);
    }

    // ---- Epilogue: acc + bias*Berr -> out
    #pragma unroll
    for (int mt = 0; mt < 4; mt++) {
        #pragma unroll
        for (int h = 0; h < 2; h++) {
            int rg = m0 + wm * 64 + mt * 16 + g + h * 8;
            if (rg < MM_) {
                float* op = out + ((size_t)b * MM_ + rg) * COUT_ + n0 + wn * 64 + tq * 2;
                #pragma unroll
                for (int nt = 0; nt < 8; nt++) {
                    float2 bb = *(const float2*)&bbs[wn * 64 + nt * 8 + tq * 2];
                    float2 v;
                    v.x = acc[mt][nt][2 * h + 0] + bb.x;
                    v.y = acc[mt][nt][2 * h + 1] + bb.y;
                    *(float2*)(op + nt * 8) = v;
                }
            }
        }
    }
}

extern "C" void kernel_launch(void* const* d_in, const int* in_sizes, int n_in,
                              void* d_out, int out_size)
{
    const float* X    = (const float*)d_in[0];
    const float* W    = (const float*)d_in[1];
    const float* bias = (const float*)d_in[2];
    const float* Werr = (const float*)d_in[3];
    const float* Berr = (const float*)d_in[4];
    float* out = (float*)d_out;

    precompute_xh<<<XR_ELEMS / (16 * 256), 256>>>(X);
    {
        dim3 gw(KTOT_ / 32, COUT_ / 64, 64);   // (36, 4, 64)
        precompute_wmh<<<gw, 256>>>(W, Werr);
    }

    cudaFuncSetAttribute(conv_mma_kernel,
                         cudaFuncAttributeMaxDynamicSharedMemorySize, SMEM_BYTES);
    dim3 grid(COUT_ / BN_, (MM_ + BM_ - 1) / BM_, 64);   // (2, 16, 64)
    conv_mma_kernel<<<grid, NTHR_, SMEM_BYTES>>>(bias, Berr, out);
}

// round 13
// speedup vs baseline: 2.3568x; 1.1545x over previous
#include <cuda_runtime.h>
#include <cuda_fp16.h>
#include <cstdint>

#define MM_    3844
#define CIN_   128
#define COUT_  256
#define KTOT_  1152
#define BM_    256
#define BN_    128
#define NTHR_  256
#define NT_    36                   // k tiles: 9 khw * 4 ci-chunks of 32

#define WM_ELEMS  (64 * KTOT_ * COUT_)
#define XR_ELEMS  (64 * 64 * 64 * CIN_)

__device__ __half g_Wmh[WM_ELEMS];   // [b][n][k], k-interleaved per 16
__device__ __half g_Xh[XR_ELEMS];    // [b][h][w][ci], k-interleaved per 16

#define STG_BYTES 36864          // A 256*96 | B 128*96 (64B data per 96B row)
#define A_OFF(s)  ((s) * STG_BYTES)
#define B_OFF(s)  ((s) * STG_BYTES + 24576)
#define BBS_OFF   (3 * STG_BYTES)          // 110592
#define SMEM_BYTES (BBS_OFF + 512)         // 111104

__device__ __forceinline__ uint32_t pack_h2(float hi, float lo) {
    uint32_t r;
    asm("cvt.rn.f16x2.f32 %0, %1, %2;" : "=r"(r) : "f"(hi), "f"(lo));
    return r;
}
__device__ __forceinline__ uint32_t smem_u32(const void* p) {
    uint32_t a;
    asm("{ .reg .u64 t; cvta.to.shared.u64 t, %1; cvt.u32.u64 %0, t; }" : "=r"(a) : "l"(p));
    return a;
}
__device__ __forceinline__ void cp16(uint32_t dst, const void* src, int src_bytes) {
    asm volatile("cp.async.cg.shared.global [%0], [%1], 16, %2;"
                 :: "r"(dst), "l"(src), "r"(src_bytes) : "memory");
}
#define CP_COMMIT() asm volatile("cp.async.commit_group;" ::: "memory")
#define CP_WAIT1()  asm volatile("cp.async.wait_group 1;" ::: "memory")

__device__ __forceinline__ void mma_f16(float c[4],
                                        uint32_t a0, uint32_t a1, uint32_t a2, uint32_t a3,
                                        uint32_t b0, uint32_t b1) {
    asm volatile(
        "mma.sync.aligned.m16n8k16.row.col.f32.f16.f16.f32 "
        "{%0,%1,%2,%3}, {%4,%5,%6,%7}, {%8,%9}, {%0,%1,%2,%3};"
        : "+f"(c[0]), "+f"(c[1]), "+f"(c[2]), "+f"(c[3])
        : "r"(a0), "r"(a1), "r"(a2), "r"(a3), "r"(b0), "r"(b1));
}

// ---- Pre-kernel 1: Xh = fp16(X), k-interleaved per 16-chunk
__global__ void __launch_bounds__(256, 4)
precompute_xh(const float* __restrict__ X)
{
    const size_t i = (size_t)blockIdx.x * 256 + threadIdx.x;   // chunk id
    const float* xp = X + i * 16;
    float v[16];
    #pragma unroll
    for (int j = 0; j < 16; j += 4) {
        float4 f = *(const float4*)(xp + j);
        v[j] = f.x; v[j+1] = f.y; v[j+2] = f.z; v[j+3] = f.w;
    }
    uint4 o0, o1;
    o0.x = pack_h2(v[1],  v[0]);  o0.y = pack_h2(v[9],  v[8]);
    o0.z = pack_h2(v[3],  v[2]);  o0.w = pack_h2(v[11], v[10]);
    o1.x = pack_h2(v[5],  v[4]);  o1.y = pack_h2(v[13], v[12]);
    o1.z = pack_h2(v[7],  v[6]);  o1.w = pack_h2(v[15], v[14]);
    uint4* op = (uint4*)(g_Xh + i * 16);
    op[0] = o0; op[1] = o1;
}

// ---- Pre-kernel 2: Wmh[b][n][k] = fp16(W*Werr) transposed, k-interleaved per 16
__global__ void __launch_bounds__(256, 2)
precompute_wmh(const float* __restrict__ W, const float* __restrict__ Werr)
{
    __shared__ __half tile[32 * 66];
    const int t  = threadIdx.x;
    const int b  = blockIdx.z;
    const int k0 = blockIdx.x * 32;
    const int n0 = blockIdx.y * 64;

    #pragma unroll
    for (int it = 0; it < 2; it++) {
        const int row = (t >> 4) + 16 * it;       // k_local
        const int nl  = (t & 15) * 4;
        const size_t gi = (size_t)(k0 + row) * COUT_ + n0 + nl;
        float4 w = *(const float4*)(W + gi);
        float4 e = *(const float4*)(Werr + (size_t)b * (KTOT_ * COUT_) + gi);
        __half* sp = tile + row * 66 + nl;
        *(uint32_t*)(sp + 0) = pack_h2(w.y * e.y, w.x * e.x);
        *(uint32_t*)(sp + 2) = pack_h2(w.w * e.w, w.z * e.z);
    }
    __syncthreads();

    const int nl = t >> 2;
    const int q  = (t & 3) >> 1;
    const int c2 = t & 1;
    const int base = c2 * 4;
    int kl[8];
    #pragma unroll
    for (int j = 0; j < 4; j += 2) {
        kl[2*j+0] = base + j;     kl[2*j+1] = base + j + 1;
        kl[2*j+2] = base + j + 8; kl[2*j+3] = base + j + 9;
    }
    const __half* sp = tile + (16 * q) * 66 + nl;
    uint4 o;
    o.x = pack_h2(__half2float(sp[kl[1] * 66]), __half2float(sp[kl[0] * 66]));
    o.y = pack_h2(__half2float(sp[kl[3] * 66]), __half2float(sp[kl[2] * 66]));
    o.z = pack_h2(__half2float(sp[kl[5] * 66]), __half2float(sp[kl[4] * 66]));
    o.w = pack_h2(__half2float(sp[kl[7] * 66]), __half2float(sp[kl[6] * 66]));
    const size_t hidx = (size_t)(b * COUT_ + n0 + nl) * KTOT_ + k0 + 16 * q + 8 * c2;
    *(uint4*)(g_Wmh + hidx) = o;
}

__global__ void __launch_bounds__(NTHR_, 1)
conv_mma_kernel(const float* __restrict__ bias,
                const float* __restrict__ Berr, float* __restrict__ out)
{
    extern __shared__ char smc[];
    const uint32_t sb = smem_u32(smc);
    float* const bbs = (float*)(smc + BBS_OFF);

    const int tid  = threadIdx.x;
    const int lane = tid & 31;
    const int wid  = tid >> 5;        // 0..7
    const int wm   = wid >> 1;        // 0..3 (M dir, 64 rows)
    const int wn   = wid & 1;         // 0..1 (N dir, 64 cols)
    const int g    = lane >> 2;       // 0..7
    const int tq   = lane & 3;        // 0..3

    const int b  = blockIdx.z;
    const int m0 = blockIdx.y * BM_;
    const int n0 = blockIdx.x * BN_;

    if (tid < BN_) bbs[tid] = bias[n0 + tid] * Berr[b * COUT_ + n0 + tid];

    // ---- A prefetch: thread = row tid, 4 cp16 (64B = 32 halfs)
    const int agm  = m0 + tid;
    const bool a_ok = (agm < MM_);
    const int amc = a_ok ? agm : 0;
    const int aho = amc / 62, awo = amc - aho * 62;
    const __half* Xp = g_Xh + (((size_t)b * 64 + aho) * 64 + awo) * CIN_;
    const int a_sz = a_ok ? 16 : 0;
    const uint32_t a_dst = sb + (uint32_t)tid * 96;

    // ---- B prefetch: thread = (row = tid>>1, 16-chunk = tid&1), 2 cp16
    const int brow = tid >> 1;
    const int bc   = tid & 1;
    const __half* Bp = g_Wmh + (size_t)(b * COUT_ + n0 + brow) * KTOT_ + 16 * bc;
    const uint32_t b_dst = sb + (uint32_t)brow * 96 + 32 * bc;

    float acc[4][8][4];
    #pragma unroll
    for (int i = 0; i < 4; i++)
        #pragma unroll
        for (int j = 0; j < 8; j++)
            #pragma unroll
            for (int q = 0; q < 4; q++) acc[i][j][q] = 0.0f;

    auto prefetch = [&](int u, int s) {
        const int khw = u >> 2, cc = u & 3;          // 32-halfs chunk
        const int kh = khw / 3, kw = khw - 3 * kh;
        const __half* asrc = Xp + (kh * 64 + kw) * CIN_ + cc * 32;
        const uint32_t ad = a_dst + A_OFF(s);
        #pragma unroll
        for (int j = 0; j < 4; j++)
            cp16(ad + 16 * j, asrc + 8 * j, a_sz);
        const int kk = khw * CIN_ + cc * 32;
        const uint32_t bd = b_dst + B_OFF(s);
        cp16(bd,      Bp + kk,     16);
        cp16(bd + 16, Bp + kk + 8, 16);
    };

    // fragment buffers: [0..3]=ar, [4..7]=a8, [8..15]=bf
    uint2 fr[2][16];
    const int arow0 = wm * 64 + g;
    const int bcol0 = wn * 64 + g;
    const int co0 = 8 * tq;          // c16=0 byte offset
    const int co1 = 32 + 8 * tq;     // c16=1 byte offset

    auto load_frags = [&](int s, int co, uint2* F) {
        const char* Ab = smc + A_OFF(s);
        const char* Bb = smc + B_OFF(s);
        #pragma unroll
        for (int mt = 0; mt < 4; mt++) {
            const int r = arow0 + mt * 16;
            F[mt]     = *(const uint2*)(Ab + r * 96 + co);
            F[4 + mt] = *(const uint2*)(Ab + (r + 8) * 96 + co);
        }
        #pragma unroll
        for (int nt = 0; nt < 8; nt++)
            F[8 + nt] = *(const uint2*)(Bb + (bcol0 + nt * 8) * 96 + co);
    };
    auto mma_set = [&](uint2* F) {
        #pragma unroll
        for (int mt = 0; mt < 4; mt++)
            #pragma unroll
            for (int nt = 0; nt < 8; nt++)
                mma_f16(acc[mt][nt], F[mt].x, F[4 + mt].x, F[mt].y, F[4 + mt].y,
                        F[8 + nt].x, F[8 + nt].y);
    };

    prefetch(0, 0); CP_COMMIT();
    prefetch(1, 1); CP_COMMIT();
    CP_WAIT1();
    __syncthreads();
    load_frags(0, co0, fr[0]);

    auto tile_step = [&](int t, int s, int sn) {
        // c16=1 frags of this stage, covered by c16=0 MMAs
        load_frags(s, co1, fr[1]);
        mma_set(fr[0]);
        if (t + 2 < NT_) prefetch(t + 2, sn == 2 ? 0 : sn + 1 == 3 ? 0 : (s + 2) % 3);
        CP_COMMIT();
        if (t + 1 < NT_) {
            CP_WAIT1();
            __syncthreads();
            // next tile c16=0 frags, covered by this tile's c16=1 MMAs
            load_frags(sn, co0, fr[0]);
        }
        mma_set(fr[1]);
    };

    #pragma unroll 1
    for (int tb = 0; tb < NT_; tb += 3) {
        tile_step(tb + 0, 0, 1);
        tile_step(tb + 1, 1, 2);
        tile_step(tb + 2, 2, 0);
    }

    // ---- Epilogue: acc + bias*Berr -> out
    #pragma unroll
    for (int mt = 0; mt < 4; mt++) {
        #pragma unroll
        for (int h = 0; h < 2; h++) {
            int rg = m0 + wm * 64 + mt * 16 + g + h * 8;
            if (rg < MM_) {
                float* op = out + ((size_t)b * MM_ + rg) * COUT_ + n0 + wn * 64 + tq * 2;
                #pragma unroll
                for (int nt = 0; nt < 8; nt++) {
                    float2 bb = *(const float2*)&bbs[wn * 64 + nt * 8 + tq * 2];
                    float2 v;
                    v.x = acc[mt][nt][2 * h + 0] + bb.x;
                    v.y = acc[mt][nt][2 * h + 1] + bb.y;
                    *(float2*)(op + nt * 8) = v;
                }
            }
        }
    }
}

extern "C" void kernel_launch(void* const* d_in, const int* in_sizes, int n_in,
                              void* d_out, int out_size)
{
    const float* X    = (const float*)d_in[0];
    const float* W    = (const float*)d_in[1];
    const float* bias = (const float*)d_in[2];
    const float* Berr = (const float*)d_in[4];
    const float* Werr = (const float*)d_in[3];
    float* out = (float*)d_out;

    precompute_xh<<<XR_ELEMS / (16 * 256), 256>>>(X);
    {
        dim3 gw(KTOT_ / 32, COUT_ / 64, 64);   // (36, 4, 64)
        precompute_wmh<<<gw, 256>>>(W, Werr);
    }

    cudaFuncSetAttribute(conv_mma_kernel,
                         cudaFuncAttributeMaxDynamicSharedMemorySize, SMEM_BYTES);
    dim3 grid(COUT_ / BN_, (MM_ + BM_ - 1) / BM_, 64);   // (2, 16, 64)
    conv_mma_kernel<<<grid, NTHR_, SMEM_BYTES>>>(bias, Berr, out);
}